// round 4
// baseline (speedup 1.0000x reference)
#include <cuda_runtime.h>

#define NN 8192
#define DD 512
#define NTHREADS_ROW 256

static __device__ float g_xn[NN * DD];                 // normalized reps (16 MB)
static __device__ int   g_lab[NN];
static __device__ float g_cos[(long long)NN * NN];     // cos matrix scratch (256 MB)
static __device__ float g_maxcos;
static __device__ float g_loss[NN];

__device__ __forceinline__ void atomicMaxF(float* addr, float val) {
    int* ia = (int*)addr;
    int old = *ia;
    while (__int_as_float(old) < val) {
        int assumed = old;
        old = atomicCAS(ia, assumed, __float_as_int(val));
        if (old == assumed) break;
    }
}

__global__ void init_kernel() {
    g_maxcos = -3.0e38f;
}

// Detect int64 vs int32 label buffer, then copy to g_lab as int32.
// int64 case: odd 32-bit words (high halves of labels 0..4095) are all zero.
// int32 case: odd words are random labels in [0,100) -> some nonzero w.h.p.
__global__ __launch_bounds__(256) void label_kernel(const int* __restrict__ lraw) {
    __shared__ int any;
    int t = threadIdx.x;
    if (t == 0) any = 0;
    __syncthreads();
    int acc = 0;
    for (int w = 1 + 2 * t; w < NN; w += 512) acc |= lraw[w];
    if (acc) atomicOr(&any, 1);
    __syncthreads();
    bool is64 = (any == 0);
    if (is64) {
        const long long* l64 = (const long long*)lraw;
        for (int i = t; i < NN; i += 256) g_lab[i] = (int)l64[i];
    } else {
        for (int i = t; i < NN; i += 256) g_lab[i] = lraw[i];
    }
}

// One block per row: compute 1/||row||, write normalized row.
__global__ __launch_bounds__(128) void normalize_kernel(const float* __restrict__ reps) {
    int i = blockIdx.x;
    int t = threadIdx.x;  // 128 threads, 4 floats each
    const float4* row = (const float4*)(reps + (size_t)i * DD);
    float4 v = row[t];
    float ss = v.x * v.x + v.y * v.y + v.z * v.z + v.w * v.w;
    #pragma unroll
    for (int o = 16; o > 0; o >>= 1) ss += __shfl_down_sync(0xffffffffu, ss, o);
    __shared__ float ws[4];
    if ((t & 31) == 0) ws[t >> 5] = ss;
    __syncthreads();
    float tot = ws[0] + ws[1] + ws[2] + ws[3];
    float nrm = sqrtf(tot);
    float rn = (nrm > 1e-20f) ? (1.0f / nrm) : 0.0f;
    float4 o4 = make_float4(v.x * rn, v.y * rn, v.z * rn, v.w * rn);
    ((float4*)(g_xn + (size_t)i * DD))[t] = o4;
}

// Symmetric Gram: compute only tiles with bx >= by (upper triangle of 128x128
// tiles), 256 threads, 8x8 microtile, BK=8, double-buffered SMEM.
// Direct store + transposed mirror store; tracks global off-diagonal max.
__global__ __launch_bounds__(256) void gram_kernel() {
    int bx = blockIdx.x, by = blockIdx.y;
    if (by > bx) return;                       // lower-triangle CTAs exit

    __shared__ float As[2][8][128];
    __shared__ float Bs[2][8][128];

    int tid = threadIdx.x;
    int tx = tid & 15;          // 0..15 -> n microtile
    int ty = tid >> 4;          // 0..15 -> m microtile
    int lr = tid >> 1;          // loader row 0..127
    int lk = (tid & 1) << 2;    // loader k offset 0 or 4

    int bm = by << 7;
    int bn = bx << 7;

    const float* Ap = g_xn + (size_t)(bm + lr) * DD + lk;
    const float* Bp = g_xn + (size_t)(bn + lr) * DD + lk;

    float4 a = *(const float4*)Ap;
    float4 b = *(const float4*)Bp;
    As[0][lk + 0][lr] = a.x; As[0][lk + 1][lr] = a.y;
    As[0][lk + 2][lr] = a.z; As[0][lk + 3][lr] = a.w;
    Bs[0][lk + 0][lr] = b.x; Bs[0][lk + 1][lr] = b.y;
    Bs[0][lk + 2][lr] = b.z; Bs[0][lk + 3][lr] = b.w;
    __syncthreads();

    float acc[8][8];
    #pragma unroll
    for (int u = 0; u < 8; u++)
        #pragma unroll
        for (int v = 0; v < 8; v++) acc[u][v] = 0.0f;

    int buf = 0;
    const int NKT = DD / 8;     // 64
    for (int kt = 0; kt < NKT; kt++) {
        if (kt < NKT - 1) {
            a = *(const float4*)(Ap + (kt + 1) * 8);
            b = *(const float4*)(Bp + (kt + 1) * 8);
        }
        #pragma unroll
        for (int kk = 0; kk < 8; kk++) {
            float av[8], bv[8];
            *(float4*)&av[0] = *(const float4*)&As[buf][kk][ty << 3];
            *(float4*)&av[4] = *(const float4*)&As[buf][kk][(ty << 3) + 4];
            *(float4*)&bv[0] = *(const float4*)&Bs[buf][kk][tx << 3];
            *(float4*)&bv[4] = *(const float4*)&Bs[buf][kk][(tx << 3) + 4];
            #pragma unroll
            for (int u = 0; u < 8; u++)
                #pragma unroll
                for (int v = 0; v < 8; v++)
                    acc[u][v] = fmaf(av[u], bv[v], acc[u][v]);
        }
        if (kt < NKT - 1) {
            int nb = buf ^ 1;
            As[nb][lk + 0][lr] = a.x; As[nb][lk + 1][lr] = a.y;
            As[nb][lk + 2][lr] = a.z; As[nb][lk + 3][lr] = a.w;
            Bs[nb][lk + 0][lr] = b.x; Bs[nb][lk + 1][lr] = b.y;
            Bs[nb][lk + 2][lr] = b.z; Bs[nb][lk + 3][lr] = b.w;
            __syncthreads();
            buf = nb;
        }
    }

    // Direct store + off-diagonal max
    float mx = -3.0e38f;
    int jb = bn + (tx << 3);
    #pragma unroll
    for (int u = 0; u < 8; u++) {
        int i = bm + (ty << 3) + u;
        float* outr = &g_cos[(size_t)i * NN + jb];
        *(float4*)outr       = make_float4(acc[u][0], acc[u][1], acc[u][2], acc[u][3]);
        *(float4*)(outr + 4) = make_float4(acc[u][4], acc[u][5], acc[u][6], acc[u][7]);
        #pragma unroll
        for (int v = 0; v < 8; v++)
            if (i != jb + v) mx = fmaxf(mx, acc[u][v]);
    }
    // Mirror (transposed) store for off-diagonal tiles; contiguous along u.
    if (bx != by) {
        int ib = bm + (ty << 3);
        #pragma unroll
        for (int v = 0; v < 8; v++) {
            int j = jb + v;
            float* outc = &g_cos[(size_t)j * NN + ib];
            *(float4*)outc       = make_float4(acc[0][v], acc[1][v], acc[2][v], acc[3][v]);
            *(float4*)(outc + 4) = make_float4(acc[4][v], acc[5][v], acc[6][v], acc[7][v]);
        }
    }

    #pragma unroll
    for (int o = 16; o > 0; o >>= 1) mx = fmaxf(mx, __shfl_down_sync(0xffffffffu, mx, o));
    __shared__ float sm[8];
    if ((tid & 31) == 0) sm[tid >> 5] = mx;
    __syncthreads();
    if (tid == 0) {
        float m = sm[0];
        #pragma unroll
        for (int w2 = 1; w2 < 8; w2++) m = fmaxf(m, sm[w2]);
        atomicMaxF(&g_maxcos, m);
    }
}

// One block per row i: accumulate pos_sum, pos_cnt, neg_exp_sum -> loss_i.
__global__ __launch_bounds__(NTHREADS_ROW) void row_kernel() {
    int i = blockIdx.x;
    int t = threadIdx.x;
    // score = ((1+cos)/2 + 1e-8)/0.1 = 5*cos + 5 + 1e-7 ; shifted by M = 5*cosmax + 5 + 1e-7
    float M = fmaf(g_maxcos, 5.0f, 5.0f + 1e-7f);
    int li = g_lab[i];
    const float* __restrict__ row = g_cos + (size_t)i * NN;

    float ps = 0.0f, cnt = 0.0f, ng = 0.0f;
    #pragma unroll 4
    for (int j = t; j < NN; j += NTHREADS_ROW) {
        float c = __ldg(row + j);
        int lj = __ldg(g_lab + j);
        float s = fmaf(c, 5.0f, 5.0f + 1e-7f) - M;
        if (j == i) continue;
        if (lj == li) { ps += s; cnt += 1.0f; }
        else          { ng += __expf(s); }
    }
    #pragma unroll
    for (int o = 16; o > 0; o >>= 1) {
        ps  += __shfl_down_sync(0xffffffffu, ps,  o);
        cnt += __shfl_down_sync(0xffffffffu, cnt, o);
        ng  += __shfl_down_sync(0xffffffffu, ng,  o);
    }
    __shared__ float sps[8], scn[8], sng[8];
    if ((t & 31) == 0) { sps[t >> 5] = ps; scn[t >> 5] = cnt; sng[t >> 5] = ng; }
    __syncthreads();
    if (t == 0) {
        float p = 0, c2 = 0, n2 = 0;
        #pragma unroll
        for (int w = 0; w < NTHREADS_ROW / 32; w++) { p += sps[w]; c2 += scn[w]; n2 += sng[w]; }
        g_loss[i] = -p / (c2 + 1e-8f) + logf(n2 + 1e-8f);
    }
}

__global__ __launch_bounds__(256) void final_kernel(float* __restrict__ out) {
    int t = threadIdx.x;
    float s = 0.0f, c = 0.0f;
    for (int i = t; i < NN; i += 256) {
        float l = g_loss[i];
        if (l > 0.0f) { s += l; c += 1.0f; }
    }
    #pragma unroll
    for (int o = 16; o > 0; o >>= 1) {
        s += __shfl_down_sync(0xffffffffu, s, o);
        c += __shfl_down_sync(0xffffffffu, c, o);
    }
    __shared__ float ssum[8], scnt[8];
    if ((t & 31) == 0) { ssum[t >> 5] = s; scnt[t >> 5] = c; }
    __syncthreads();
    if (t == 0) {
        float S = 0, C = 0;
        #pragma unroll
        for (int w = 0; w < 8; w++) { S += ssum[w]; C += scnt[w]; }
        out[0] = S / (C + 1e-8f);
    }
}

extern "C" void kernel_launch(void* const* d_in, const int* in_sizes, int n_in,
                              void* d_out, int out_size) {
    (void)in_sizes; (void)n_in; (void)out_size;
    const float* reps = (const float*)d_in[0];
    const int*   lraw = (const int*)d_in[1];
    float*       out  = (float*)d_out;

    init_kernel<<<1, 1>>>();
    label_kernel<<<1, 256>>>(lraw);
    normalize_kernel<<<NN, 128>>>(reps);
    dim3 grid(NN / 128, NN / 128);
    gram_kernel<<<grid, 256>>>();
    row_kernel<<<NN, NTHREADS_ROW>>>();
    final_kernel<<<1, 256>>>(out);
}

// round 8
// speedup vs baseline: 1.8098x; 1.8098x over previous
#include <cuda_runtime.h>
#include <cuda_bf16.h>
#include <cstdint>

#define NN 8192
#define DD 512
#define NCLS 100

// ---------------------------------------------------------------------------
// Device globals
// ---------------------------------------------------------------------------
static __device__ __nv_bfloat16 g_hi[NN * DD];   // 8 MB
static __device__ __nv_bfloat16 g_lo[NN * DD];   // 8 MB
static __device__ int   g_lab[NN];
static __device__ float g_cnt[NN];               // (#same-label) - 1
static __device__ float g_ps[NN];                // sum of pos scores (raw)
static __device__ float g_ng[NN];                // sum of exp(neg scores)

// ---------------------------------------------------------------------------
// Baseline-ISA PTX helpers (no 'a'-features: works at target sm_103)
// ---------------------------------------------------------------------------
__device__ __forceinline__ uint32_t smem_u32(const void* p) {
    uint32_t a;
    asm("{ .reg .u64 t; cvta.to.shared.u64 t, %1; cvt.u32.u64 %0, t; }" : "=r"(a) : "l"(p));
    return a;
}

#define CP_ASYNC16(saddr, gaddr) \
    asm volatile("cp.async.cg.shared.global [%0], [%1], 16;" :: "r"(saddr), "l"(gaddr) : "memory")
#define CP_COMMIT() asm volatile("cp.async.commit_group;" ::: "memory")
#define CP_WAIT0()  asm volatile("cp.async.wait_group 0;" ::: "memory")
#define CP_WAIT1()  asm volatile("cp.async.wait_group 1;" ::: "memory")

#define LDSM4(r0, r1, r2, r3, addr) \
    asm volatile("ldmatrix.sync.aligned.m8n8.x4.shared.b16 {%0,%1,%2,%3}, [%4];" \
                 : "=r"(r0), "=r"(r1), "=r"(r2), "=r"(r3) : "r"(addr))

#define MMA16816(c, a0, a1, a2, a3, b0, b1) \
    asm volatile("mma.sync.aligned.m16n8k16.row.col.f32.bf16.bf16.f32 " \
                 "{%0,%1,%2,%3}, {%4,%5,%6,%7}, {%8,%9}, {%0,%1,%2,%3};" \
                 : "+f"((c)[0]), "+f"((c)[1]), "+f"((c)[2]), "+f"((c)[3]) \
                 : "r"(a0), "r"(a1), "r"(a2), "r"(a3), "r"(b0), "r"(b1))

// ---------------------------------------------------------------------------
// Small kernels
// ---------------------------------------------------------------------------
__global__ __launch_bounds__(256) void init_sums_kernel() {
    int i = blockIdx.x * 256 + threadIdx.x;
    if (i < NN) { g_ps[i] = 0.0f; g_ng[i] = 0.0f; }
}

// Detect int64 vs int32 labels, fill g_lab, build per-row same-label count.
__global__ __launch_bounds__(256) void label_kernel(const int* __restrict__ lraw) {
    __shared__ int any;
    __shared__ int hist[NCLS];
    int t = threadIdx.x;
    if (t == 0) any = 0;
    if (t < NCLS) hist[t] = 0;
    __syncthreads();
    int acc = 0;
    for (int w = 1 + 2 * t; w < NN; w += 512) acc |= lraw[w];
    if (acc) atomicOr(&any, 1);
    __syncthreads();
    bool is64 = (any == 0);
    if (is64) {
        const long long* l64 = (const long long*)lraw;
        for (int i = t; i < NN; i += 256) g_lab[i] = (int)l64[i];
    } else {
        for (int i = t; i < NN; i += 256) g_lab[i] = lraw[i];
    }
    __syncthreads();
    for (int i = t; i < NN; i += 256) atomicAdd(&hist[g_lab[i]], 1);
    __syncthreads();
    for (int i = t; i < NN; i += 256) g_cnt[i] = (float)(hist[g_lab[i]] - 1);
}

// Normalize each row, split into bf16 hi + lo.
__global__ __launch_bounds__(128) void prep_kernel(const float* __restrict__ reps) {
    int i = blockIdx.x;
    int t = threadIdx.x;
    const float4* row = (const float4*)(reps + (size_t)i * DD);
    float4 v = row[t];
    float ss = v.x * v.x + v.y * v.y + v.z * v.z + v.w * v.w;
    #pragma unroll
    for (int o = 16; o > 0; o >>= 1) ss += __shfl_down_sync(0xffffffffu, ss, o);
    __shared__ float ws[4];
    if ((t & 31) == 0) ws[t >> 5] = ss;
    __syncthreads();
    float tot = ws[0] + ws[1] + ws[2] + ws[3];
    float nrm = sqrtf(tot);
    float rn = (nrm > 1e-20f) ? (1.0f / nrm) : 0.0f;
    float x[4] = {v.x * rn, v.y * rn, v.z * rn, v.w * rn};
    __nv_bfloat16 h[4], l[4];
    #pragma unroll
    for (int q = 0; q < 4; q++) {
        h[q] = __float2bfloat16(x[q]);
        l[q] = __float2bfloat16(x[q] - __bfloat162float(h[q]));
    }
    size_t base = (size_t)i * DD + (size_t)t * 4;
    __nv_bfloat162* hp = (__nv_bfloat162*)(g_hi + base);
    __nv_bfloat162* lp = (__nv_bfloat162*)(g_lo + base);
    hp[0] = __nv_bfloat162{h[0], h[1]}; hp[1] = __nv_bfloat162{h[2], h[3]};
    lp[0] = __nv_bfloat162{l[0], l[1]}; lp[1] = __nv_bfloat162{l[2], l[3]};
}

// ---------------------------------------------------------------------------
// Fused HMMA Gram + contrastive row-sum epilogue.
// 128x128 tile per CTA, upper-triangular tiles only.  G = hi.hi + hi.lo + lo.hi.
// 8 warps (2x4): each warp 64x32 via m16n8k16.  KC=32, cp.async double buffer.
// SMEM rows padded to 80B stride -> conflict-free ldmatrix.
// ---------------------------------------------------------------------------
#define KC 32
#define ROWB 80                         // bytes per smem row (64 data + 16 pad)
#define TILEB (128 * ROWB)              // 10240 B per matrix
#define BUFB (4 * TILEB)                // Ahi, Alo, Bhi, Blo
#define DSMEM_BYTES (2 * BUFB)          // 81920

__global__ __launch_bounds__(256) void gram_kernel() {
    int bx = blockIdx.x, by = blockIdx.y;
    if (by > bx) return;

    extern __shared__ char dsmem[];
    __shared__ float s_rps[128], s_rng[128], s_cps[128], s_cng[128];
    __shared__ int s_labA[128], s_labB[128];

    int tid = threadIdx.x;
    int lane = tid & 31;
    int wid = tid >> 5;
    int warp_m = wid >> 2;       // 0..1
    int warp_n = wid & 3;        // 0..3
    bool diag = (bx == by);
    int bm = by << 7, bn = bx << 7;

    uint32_t sbase = smem_u32(dsmem);

    if (tid < 128) {
        s_labA[tid] = g_lab[bm + tid];
        s_labB[tid] = g_lab[bn + tid];
        s_rps[tid] = 0.0f; s_rng[tid] = 0.0f;
        s_cps[tid] = 0.0f; s_cng[tid] = 0.0f;
    }

    // ---- async tile loader (chunk c -> buffer b) ----
    auto load_chunk = [&](int c, int b) {
        int k0 = c * KC;
        uint32_t sb = sbase + b * BUFB;
        #pragma unroll
        for (int m = 0; m < 4; m++) {
            const __nv_bfloat16* gsrc = (m & 1) ? g_lo : g_hi;
            int rbase = (m < 2) ? bm : bn;
            uint32_t smat = sb + m * TILEB;
            #pragma unroll
            for (int it = 0; it < 2; it++) {
                int u = tid + it * 256;       // 0..511
                int row = u >> 2;             // 0..127
                int seg = u & 3;              // 16B segments
                const void* g = gsrc + (size_t)(rbase + row) * DD + k0 + seg * 8;
                uint32_t s = smat + row * ROWB + seg * 16;
                CP_ASYNC16(s, g);
            }
        }
    };

    float acc[4][4][4];
    #pragma unroll
    for (int mt = 0; mt < 4; mt++)
        #pragma unroll
        for (int nt = 0; nt < 4; nt++)
            #pragma unroll
            for (int e = 0; e < 4; e++) acc[mt][nt][e] = 0.0f;

    load_chunk(0, 0);
    CP_COMMIT();

    const int NCHUNK = DD / KC;  // 16
    for (int c = 0; c < NCHUNK; c++) {
        if (c < NCHUNK - 1) { load_chunk(c + 1, (c + 1) & 1); CP_COMMIT(); CP_WAIT1(); }
        else                { CP_WAIT0(); }
        __syncthreads();

        uint32_t ab  = sbase + (c & 1) * BUFB;          // Ahi
        uint32_t alb = ab + TILEB;                      // Alo
        uint32_t bb  = ab + 2 * TILEB;                  // Bhi
        uint32_t blb = ab + 3 * TILEB;                  // Blo

        #pragma unroll
        for (int ks = 0; ks < 2; ks++) {
            int k0 = ks * 16;
            // B fragments: x4 covers two n-tiles (16 n-rows) at k0/k0+8
            uint32_t bh[8], bl[8];
            #pragma unroll
            for (int p = 0; p < 2; p++) {
                int nrow = warp_n * 32 + p * 16 + (lane & 7) + ((lane >> 4) << 3);
                int koff = k0 + ((lane >> 3) & 1) * 8;
                uint32_t boff = nrow * ROWB + koff * 2;
                LDSM4(bh[p*4+0], bh[p*4+1], bh[p*4+2], bh[p*4+3], bb + boff);
                LDSM4(bl[p*4+0], bl[p*4+1], bl[p*4+2], bl[p*4+3], blb + boff);
            }
            #pragma unroll
            for (int mt = 0; mt < 4; mt++) {
                int arow = warp_m * 64 + mt * 16 + (lane & 15);
                int koff = k0 + (lane >> 4) * 8;
                uint32_t aoff = arow * ROWB + koff * 2;
                uint32_t ah0, ah1, ah2, ah3, al0, al1, al2, al3;
                LDSM4(ah0, ah1, ah2, ah3, ab + aoff);
                LDSM4(al0, al1, al2, al3, alb + aoff);
                #pragma unroll
                for (int nt = 0; nt < 4; nt++) {
                    int bi = (nt >> 1) * 4 + (nt & 1) * 2;
                    MMA16816(acc[mt][nt], ah0, ah1, ah2, ah3, bh[bi], bh[bi+1]);
                    MMA16816(acc[mt][nt], ah0, ah1, ah2, ah3, bl[bi], bl[bi+1]);
                    MMA16816(acc[mt][nt], al0, al1, al2, al3, bh[bi], bh[bi+1]);
                }
            }
        }
        __syncthreads();
    }

    // ---------------- fused contrastive epilogue ----------------
    int qid = lane >> 2;        // 0..7
    int cpos = lane & 3;        // 0..3
    float rowPS[4][2], rowNG[4][2], colPS[4][2], colNG[4][2];
    #pragma unroll
    for (int a = 0; a < 4; a++)
        #pragma unroll
        for (int h = 0; h < 2; h++) {
            rowPS[a][h] = 0.0f; rowNG[a][h] = 0.0f;
            colPS[a][h] = 0.0f; colNG[a][h] = 0.0f;
        }

    #pragma unroll
    for (int mt = 0; mt < 4; mt++) {
        #pragma unroll
        for (int half = 0; half < 2; half++) {
            int il = warp_m * 64 + mt * 16 + qid + half * 8;
            int li = s_labA[il];
            int gi = bm + il;
            #pragma unroll
            for (int nt = 0; nt < 4; nt++) {
                #pragma unroll
                for (int b = 0; b < 2; b++) {
                    int jl = warp_n * 32 + nt * 8 + cpos * 2 + b;
                    float g = acc[mt][nt][half * 2 + b];
                    float s = fmaf(g, 5.0f, 5.0f + 1e-7f);
                    bool same = (s_labB[jl] == li);
                    bool isd = (gi == bn + jl);
                    float pc = (same && !isd) ? s : 0.0f;
                    float e  = same ? 0.0f : __expf(s);
                    rowPS[mt][half] += pc;  rowNG[mt][half] += e;
                    colPS[nt][b]    += pc;  colNG[nt][b]    += e;
                }
            }
        }
    }
    #pragma unroll
    for (int mt = 0; mt < 4; mt++)
        #pragma unroll
        for (int half = 0; half < 2; half++) {
            int il = warp_m * 64 + mt * 16 + qid + half * 8;
            atomicAdd(&s_rps[il], rowPS[mt][half]);
            atomicAdd(&s_rng[il], rowNG[mt][half]);
        }
    if (!diag) {
        #pragma unroll
        for (int nt = 0; nt < 4; nt++)
            #pragma unroll
            for (int b = 0; b < 2; b++) {
                int jl = warp_n * 32 + nt * 8 + cpos * 2 + b;
                atomicAdd(&s_cps[jl], colPS[nt][b]);
                atomicAdd(&s_cng[jl], colNG[nt][b]);
            }
    }
    __syncthreads();
    if (tid < 128) {
        atomicAdd(&g_ps[bm + tid], s_rps[tid]);
        atomicAdd(&g_ng[bm + tid], s_rng[tid]);
        if (!diag) {
            atomicAdd(&g_ps[bn + tid], s_cps[tid]);
            atomicAdd(&g_ng[bn + tid], s_cng[tid]);
        }
    }
}

// ---------------------------------------------------------------------------
// Final: loss_i = -ps/(cnt+eps) + log(ng+eps); masked mean of loss>0.
// (Global max-shift cancels analytically to ~1e-9 absolute — omitted.)
// ---------------------------------------------------------------------------
__global__ __launch_bounds__(256) void loss_kernel(float* __restrict__ out) {
    int t = threadIdx.x;
    float s = 0.0f, c = 0.0f;
    for (int i = t; i < NN; i += 256) {
        float l = -g_ps[i] / (g_cnt[i] + 1e-8f) + logf(g_ng[i] + 1e-8f);
        if (l > 0.0f) { s += l; c += 1.0f; }
    }
    #pragma unroll
    for (int o = 16; o > 0; o >>= 1) {
        s += __shfl_down_sync(0xffffffffu, s, o);
        c += __shfl_down_sync(0xffffffffu, c, o);
    }
    __shared__ float ssum[8], scnt[8];
    if ((t & 31) == 0) { ssum[t >> 5] = s; scnt[t >> 5] = c; }
    __syncthreads();
    if (t == 0) {
        float S = 0.0f, C = 0.0f;
        #pragma unroll
        for (int w = 0; w < 8; w++) { S += ssum[w]; C += scnt[w]; }
        out[0] = S / (C + 1e-8f);
    }
}

// ---------------------------------------------------------------------------
extern "C" void kernel_launch(void* const* d_in, const int* in_sizes, int n_in,
                              void* d_out, int out_size) {
    (void)in_sizes; (void)n_in; (void)out_size;
    const float* reps = (const float*)d_in[0];
    const int*   lraw = (const int*)d_in[1];
    float*       out  = (float*)d_out;

    cudaFuncSetAttribute(gram_kernel, cudaFuncAttributeMaxDynamicSharedMemorySize,
                         DSMEM_BYTES);

    init_sums_kernel<<<(NN + 255) / 256, 256>>>();
    label_kernel<<<1, 256>>>(lraw);
    prep_kernel<<<NN, 128>>>(reps);
    dim3 grid(NN / 128, NN / 128);
    gram_kernel<<<grid, 256, DSMEM_BYTES>>>();
    loss_kernel<<<1, 256>>>(out);
}